// round 12
// baseline (speedup 1.0000x reference)
#include <cuda_runtime.h>
#include <cuda_fp16.h>
#include <cstdint>

// Problem dims
#define NN   8192
#define DIN  128
#define DOUT 64

// GEMM tiling: fp32 A staged, conversion in registers at fragment load
#define M_TILE  128
#define K_TILE  32
#define SPLITK  4
#define KPER    (NN / SPLITK)      // 2048
#define NCHUNK  (KPER / K_TILE)    // 64
#define STAGES  5

#define A32_STAGE_BYTES (M_TILE * 128)              // 128 rows x 32 fp32 = 16 KB
#define B_STAGE_BYTES   (K_TILE * 128)              // 32 rows x 128B = 4 KB
#define SMEM_B_BASE     (STAGES * A32_STAGE_BYTES)  // 80 KB
#define SMEM_TOTAL      (SMEM_B_BASE + STAGES * B_STAGE_BYTES)   // 100 KB -> 2 CTAs/SM

// Scratch (no cudaMalloc allowed)
__device__ __align__(16) float  g_deg[NN];
__device__ __align__(16) __half g_yh[(size_t)NN * DOUT];              // Y = d^-1/2*(X@W), fp16
__device__ __align__(16) float  g_hpart[SPLITK][(size_t)NN * DOUT];   // split-K partials
__device__ int g_ticket[NN / M_TILE];                                 // zero-init; reset each run

// ---------------------------------------------------------------------------
// PTX helpers (generic PTX only)
// ---------------------------------------------------------------------------
__device__ __forceinline__ uint32_t smem_u32(const void* p) {
    uint32_t a;
    asm("{ .reg .u64 t; cvta.to.shared.u64 t, %1; cvt.u32.u64 %0, t; }" : "=r"(a) : "l"(p));
    return a;
}

#define CP_ASYNC16(dst, src) \
    asm volatile("cp.async.cg.shared.global [%0], [%1], 16;" :: "r"(dst), "l"(src) : "memory")
#define CP_COMMIT() asm volatile("cp.async.commit_group;" ::: "memory")
#define CP_WAIT3()  asm volatile("cp.async.wait_group 3;" ::: "memory")

__device__ __forceinline__ void ldsm_x4_t(uint32_t r[4], uint32_t addr) {
    asm volatile("ldmatrix.sync.aligned.m8n8.x4.trans.shared.b16 {%0,%1,%2,%3}, [%4];"
                 : "=r"(r[0]), "=r"(r[1]), "=r"(r[2]), "=r"(r[3]) : "r"(addr));
}
__device__ __forceinline__ void mma_f16(float c[4], const uint32_t a[4], uint32_t b0, uint32_t b1) {
    asm volatile(
        "mma.sync.aligned.m16n8k16.row.col.f32.f16.f16.f32 "
        "{%0,%1,%2,%3}, {%4,%5,%6,%7}, {%8,%9}, {%0,%1,%2,%3};"
        : "+f"(c[0]), "+f"(c[1]), "+f"(c[2]), "+f"(c[3])
        : "r"(a[0]), "r"(a[1]), "r"(a[2]), "r"(a[3]), "r"(b0), "r"(b1));
}

// load float2 from smem, convert to packed fp16x2 {lo, hi} (== __floats2half2_rn)
__device__ __forceinline__ uint32_t lds_cvt_h2(uint32_t addr) {
    float lo, hi;
    asm volatile("ld.shared.v2.f32 {%0,%1}, [%2];" : "=f"(lo), "=f"(hi) : "r"(addr));
    uint32_t r;
    asm volatile("cvt.rn.f16x2.f32 %0, %1, %2;" : "=r"(r) : "f"(hi), "f"(lo));
    return r;
}

// ---------------------------------------------------------------------------
// Kernel 1: deg[i] = rowsum(A[i])  — pure 256 MB read @ HBM cap (42.3us measured)
// ---------------------------------------------------------------------------
__global__ void __launch_bounds__(256)
rowsum_kernel(const float* __restrict__ A) {
    __shared__ float red[8];
    for (int row = blockIdx.x; row < NN; row += gridDim.x) {
        const float4* a = reinterpret_cast<const float4*>(A + (size_t)row * NN);
        float s = 0.f;
        #pragma unroll 8
        for (int i = threadIdx.x; i < NN / 4; i += 256) {
            float4 v = a[i];
            s += (v.x + v.y) + (v.z + v.w);
        }
        #pragma unroll
        for (int o = 16; o; o >>= 1) s += __shfl_xor_sync(0xFFFFFFFFu, s, o);
        if ((threadIdx.x & 31) == 0) red[threadIdx.x >> 5] = s;
        __syncthreads();
        if (threadIdx.x < 32) {
            s = (threadIdx.x < 8) ? red[threadIdx.x] : 0.f;
            #pragma unroll
            for (int o = 4; o; o >>= 1) s += __shfl_xor_sync(0xFFFFFFFFu, s, o);
            if (threadIdx.x == 0) g_deg[row] = s;
        }
        __syncthreads();
    }
}

// ---------------------------------------------------------------------------
// Kernel 2: Y[j][k] = fp16( rsqrt(deg[j]) * sum_f X[j][f] * W[f][k] )
// ---------------------------------------------------------------------------
__global__ void xw_kernel(const float* __restrict__ X, const float* __restrict__ W) {
    __shared__ float sW[DIN * DOUT];   // 32 KB
    __shared__ float sX[16 * DIN];     // 8 KB
    int r0 = blockIdx.x * 16;
    for (int i = threadIdx.x; i < DIN * DOUT; i += 256) sW[i] = W[i];
    for (int i = threadIdx.x; i < 16 * DIN; i += 256) {
        int r = i >> 7, f = i & 127;
        sX[i] = X[(size_t)(r0 + r) * DIN + f] * rsqrtf(g_deg[r0 + r]);
    }
    __syncthreads();

    int r  = threadIdx.x >> 4;
    int c0 = (threadIdx.x & 15) * 4;
    float4 acc = make_float4(0.f, 0.f, 0.f, 0.f);
    #pragma unroll 8
    for (int f = 0; f < DIN; f++) {
        float s = sX[r * DIN + f];
        float4 w = *reinterpret_cast<const float4*>(&sW[f * DOUT + c0]);
        acc.x += s * w.x; acc.y += s * w.y; acc.z += s * w.z; acc.w += s * w.w;
    }
    __half2 h01 = __floats2half2_rn(acc.x, acc.y);
    __half2 h23 = __floats2half2_rn(acc.z, acc.w);
    uint2 u;
    u.x = *reinterpret_cast<uint32_t*>(&h01);
    u.y = *reinterpret_cast<uint32_t*>(&h23);
    *reinterpret_cast<uint2*>(&g_yh[(size_t)(r0 + r) * DOUT + c0]) = u;
}

// ---------------------------------------------------------------------------
// Kernel 3: split-K GEMM, fp32 A staged 5-deep; A-fragments built by
// LDS.64 + cvt directly into mma layout (NO fp16 A buffer, no extra syncs).
// grid (64, 4), block 256 (8 warps: 4 over M x 2 over N)
// Fused last-CTA reduction writes relu(d^-1/2 * sum partials) to out.
// ---------------------------------------------------------------------------
__device__ __forceinline__ void load_chunk(uint32_t sbase, int stage, int c,
                                           const float* __restrict__ Ablk,
                                           const __half* __restrict__ Bblk, int tid) {
    const uint32_t sA = sbase + (uint32_t)stage * A32_STAGE_BYTES;
    const uint32_t sB = sbase + SMEM_B_BASE + (uint32_t)stage * B_STAGE_BYTES;
    const float*  ap = Ablk + (size_t)c * K_TILE;
    const __half* bp = Bblk + (size_t)c * K_TILE * DOUT;
    // A fp32: 128 rows x 128B -> 1024 x 16B -> 4 per thread
    #pragma unroll
    for (int it = 0; it < 4; it++) {
        int idx = tid + 256 * it;
        int row = idx >> 3;
        int cc  = idx & 7;
        uint32_t dst = sA + (uint32_t)row * 128 + ((uint32_t)(cc ^ (row & 7)) << 4);
        CP_ASYNC16(dst, ap + (size_t)row * NN + cc * 4);
    }
    // B fp16: 32 rows x 128B -> 256 x 16B -> 1 per thread
    {
        int kr  = tid >> 3;
        int cc  = tid & 7;
        uint32_t dst = sB + (uint32_t)kr * 128 + ((uint32_t)(cc ^ (kr & 7)) << 4);
        CP_ASYNC16(dst, bp + (size_t)kr * DOUT + cc * 8);
    }
}

__global__ void __launch_bounds__(256, 2)
gemm_kernel(const float* __restrict__ A, float* __restrict__ out) {
    extern __shared__ __align__(128) char smem[];
    const uint32_t sbase = smem_u32(smem);

    const int tid  = threadIdx.x;
    const int lane = tid & 31;
    const int wid  = tid >> 5;
    const int wm   = wid & 3;            // warp M group (32 rows)
    const int wn   = wid >> 2;           // warp N group (32 cols)
    const int Ar0  = wm * 32;
    const int Cn0  = wn * 32;

    const float*  Ablk = A + (size_t)blockIdx.x * M_TILE * NN + (size_t)blockIdx.y * KPER;
    const __half* Bblk = g_yh + (size_t)blockIdx.y * KPER * DOUT;

    // mma A-fragment lane geometry: g = lane>>2 (row), q = lane&3 (col pair)
    const int fg = lane >> 2;
    const int fq = lane & 3;
    // B ldsm lane geometry
    const int b_lk  = lane & 15;
    const int b_ln8 = lane >> 4;

    float acc[2][4][4];
    #pragma unroll
    for (int mi = 0; mi < 2; mi++)
        #pragma unroll
        for (int ni = 0; ni < 4; ni++)
            #pragma unroll
            for (int q = 0; q < 4; q++) acc[mi][ni][q] = 0.f;

    // prologue: chunks 0..3 -> stages 0..3 (4 groups pending)
    #pragma unroll
    for (int s = 0; s < STAGES - 1; s++) {
        load_chunk(sbase, s, s, Ablk, Bblk, tid);
        CP_COMMIT();
    }

    for (int c = 0; c < NCHUNK; c++) {
        CP_WAIT3();                       // <=3 younger pending -> chunk c resident
        __syncthreads();                  // frees stage (c-1)%5 for refill

        const int s = c % STAGES;
        const uint32_t sA32 = sbase + (uint32_t)s * A32_STAGE_BYTES;
        const uint32_t sB   = sbase + SMEM_B_BASE + (uint32_t)s * B_STAGE_BYTES;

        // prefetch chunk c+4 into stage (c+4)%5 == (c-1)%5; commit EVERY iter
        if (c + STAGES - 1 < NCHUNK)
            load_chunk(sbase, (c + STAGES - 1) % STAGES, c + STAGES - 1, Ablk, Bblk, tid);
        CP_COMMIT();

        // compute chunk c: A fragments straight from fp32 smem (LDS.64 + cvt)
        #pragma unroll
        for (int kk = 0; kk < K_TILE / 16; kk++) {
            uint32_t af[2][4];
            #pragma unroll
            for (int mi = 0; mi < 2; mi++) {
                const int r0 = Ar0 + mi * 16 + fg;
                const int r1 = r0 + 8;
                const uint32_t rx0 = (uint32_t)(r0 & 7);
                const uint32_t rx1 = (uint32_t)(r1 & 7);
                const uint32_t base0 = sA32 + (uint32_t)r0 * 128 + (uint32_t)(fq & 1) * 8;
                const uint32_t base1 = sA32 + (uint32_t)r1 * 128 + (uint32_t)(fq & 1) * 8;
                const uint32_t uL = (uint32_t)(kk * 4 + (fq >> 1));      // cols kk*16+2q
                const uint32_t uH = uL + 2;                               // cols +8
                af[mi][0] = lds_cvt_h2(base0 + ((uL ^ rx0) << 4));
                af[mi][1] = lds_cvt_h2(base1 + ((uL ^ rx1) << 4));
                af[mi][2] = lds_cvt_h2(base0 + ((uH ^ rx0) << 4));
                af[mi][3] = lds_cvt_h2(base1 + ((uH ^ rx1) << 4));
            }
            uint32_t bf[2][4];
            #pragma unroll
            for (int nb = 0; nb < 2; nb++) {
                int kr = kk * 16 + b_lk;
                int n  = Cn0 + nb * 16 + b_ln8 * 8;
                uint32_t addr = sB + (uint32_t)kr * 128 +
                                ((uint32_t)((n >> 3) ^ (kr & 7)) << 4);
                ldsm_x4_t(bf[nb], addr);
            }
            #pragma unroll
            for (int mi = 0; mi < 2; mi++)
                #pragma unroll
                for (int ni = 0; ni < 4; ni++)
                    mma_f16(acc[mi][ni], af[mi], bf[ni >> 1][2 * (ni & 1)], bf[ni >> 1][2 * (ni & 1) + 1]);
        }
    }

    // epilogue: acc -> g_hpart[split]
    float* Hp = g_hpart[blockIdx.y];
    const int g = lane >> 2, q = lane & 3;
    const int R0 = blockIdx.x * M_TILE + wm * 32;
    #pragma unroll
    for (int mi = 0; mi < 2; mi++) {
        #pragma unroll
        for (int ni = 0; ni < 4; ni++) {
            int row = R0 + mi * 16 + g;
            int col = Cn0 + ni * 8 + q * 2;
            *reinterpret_cast<float2*>(&Hp[(size_t)row * DOUT + col]) =
                make_float2(acc[mi][ni][0], acc[mi][ni][1]);
            *reinterpret_cast<float2*>(&Hp[(size_t)(row + 8) * DOUT + col]) =
                make_float2(acc[mi][ni][2], acc[mi][ni][3]);
        }
    }

    // fused final reduction: last CTA of this mtile sums the 4 partials
    __syncthreads();
    __shared__ int isLast;
    if (tid == 0) {
        __threadfence();
        int old = atomicAdd(&g_ticket[blockIdx.x], 1);
        isLast = (old == SPLITK - 1);
    }
    __syncthreads();
    if (isLast) {
        const int base_row = blockIdx.x * M_TILE;
        #pragma unroll
        for (int it = 0; it < 8; it++) {
            int i = tid + 256 * it;
            int r  = i >> 4;
            int c4 = (i & 15) * 4;
            size_t o = (size_t)(base_row + r) * DOUT + c4;
            float4 a = *reinterpret_cast<const float4*>(&g_hpart[0][o]);
            float4 b = *reinterpret_cast<const float4*>(&g_hpart[1][o]);
            float4 cc = *reinterpret_cast<const float4*>(&g_hpart[2][o]);
            float4 d = *reinterpret_cast<const float4*>(&g_hpart[3][o]);
            float sc = rsqrtf(g_deg[base_row + r]);
            float4 rr;
            rr.x = fmaxf((a.x + b.x + cc.x + d.x) * sc, 0.f);
            rr.y = fmaxf((a.y + b.y + cc.y + d.y) * sc, 0.f);
            rr.z = fmaxf((a.z + b.z + cc.z + d.z) * sc, 0.f);
            rr.w = fmaxf((a.w + b.w + cc.w + d.w) * sc, 0.f);
            *reinterpret_cast<float4*>(&out[o]) = rr;
        }
        if (tid == 0) g_ticket[blockIdx.x] = 0;   // reset for next graph replay
    }
}

// ---------------------------------------------------------------------------
// Launch
// ---------------------------------------------------------------------------
extern "C" void kernel_launch(void* const* d_in, const int* in_sizes, int n_in,
                              void* d_out, int out_size) {
    const float* X = (const float*)d_in[0];   // features      [8192, 128]
    const float* A = (const float*)d_in[1];   // adjacency     [8192, 8192]
    const float* W = (const float*)d_in[2];   // weight        [128, 64]
    float* out = (float*)d_out;               // [8192, 64] fp32
    (void)in_sizes; (void)n_in; (void)out_size;

    static bool attr_set = false;
    if (!attr_set) {
        cudaFuncSetAttribute(gemm_kernel, cudaFuncAttributeMaxDynamicSharedMemorySize, SMEM_TOTAL);
        attr_set = true;
    }

    rowsum_kernel<<<1184, 256>>>(A);           // pure 256 MB read @ HBM cap
    xw_kernel<<<NN / 16, 256>>>(X, W);
    gemm_kernel<<<dim3(NN / M_TILE, SPLITK), 256, SMEM_TOTAL>>>(A, out);
}

// round 13
// speedup vs baseline: 1.1578x; 1.1578x over previous
#include <cuda_runtime.h>
#include <cuda_fp16.h>
#include <cstdint>

// Problem dims
#define NN   8192
#define DIN  128
#define DOUT 64

// GEMM tiling (R5-proven config)
#define M_TILE  128
#define K_TILE  64
#define SPLITK  4
#define KPER    (NN / SPLITK)      // 2048
#define NCHUNK  (KPER / K_TILE)    // 32
#define STAGES  4

#define A_STAGE_BYTES (M_TILE * 128)            // 16 KB
#define B_STAGE_BYTES (K_TILE * 128)            // 8 KB
#define SMEM_B_BASE   (STAGES * A_STAGE_BYTES)  // 64 KB
#define SMEM_TOTAL    (STAGES * (A_STAGE_BYTES + B_STAGE_BYTES))  // 96 KB -> 2 CTAs/SM

// Scratch (no cudaMalloc allowed)
__device__ __align__(16)  float  g_deg[NN];
__device__ __align__(16)  __half g_ah[(size_t)NN * NN];                   // fp16 copy of A
__device__ __align__(16)  __half g_yh[(size_t)NN * DOUT];                 // Y = d^-1/2*(X@W), fp16
__device__ __align__(16)  __half g_hpart[SPLITK][(size_t)NN * DOUT];      // split-K partials (fp16)

// ---------------------------------------------------------------------------
// PTX helpers (generic PTX only — harness compiles through compute_103 base)
// ---------------------------------------------------------------------------
__device__ __forceinline__ uint32_t smem_u32(const void* p) {
    uint32_t a;
    asm("{ .reg .u64 t; cvta.to.shared.u64 t, %1; cvt.u32.u64 %0, t; }" : "=r"(a) : "l"(p));
    return a;
}

#define CP_ASYNC16(dst, src) \
    asm volatile("cp.async.cg.shared.global [%0], [%1], 16;" :: "r"(dst), "l"(src) : "memory")
#define CP_COMMIT() asm volatile("cp.async.commit_group;" ::: "memory")
#define CP_WAIT2()  asm volatile("cp.async.wait_group 2;" ::: "memory")

__device__ __forceinline__ void ldsm_x4(uint32_t r[4], uint32_t addr) {
    asm volatile("ldmatrix.sync.aligned.m8n8.x4.shared.b16 {%0,%1,%2,%3}, [%4];"
                 : "=r"(r[0]), "=r"(r[1]), "=r"(r[2]), "=r"(r[3]) : "r"(addr));
}
__device__ __forceinline__ void ldsm_x4_t(uint32_t r[4], uint32_t addr) {
    asm volatile("ldmatrix.sync.aligned.m8n8.x4.trans.shared.b16 {%0,%1,%2,%3}, [%4];"
                 : "=r"(r[0]), "=r"(r[1]), "=r"(r[2]), "=r"(r[3]) : "r"(addr));
}
__device__ __forceinline__ void mma_f16(float c[4], const uint32_t a[4], uint32_t b0, uint32_t b1) {
    asm volatile(
        "mma.sync.aligned.m16n8k16.row.col.f32.f16.f16.f32 "
        "{%0,%1,%2,%3}, {%4,%5,%6,%7}, {%8,%9}, {%0,%1,%2,%3};"
        : "+f"(c[0]), "+f"(c[1]), "+f"(c[2]), "+f"(c[3])
        : "r"(a[0]), "r"(a[1]), "r"(a[2]), "r"(a[3]), "r"(b0), "r"(b1));
}

// ---------------------------------------------------------------------------
// Kernel 1: deg[i] = rowsum(A[i]); also writes A_h = fp16(A)   (R5 verbatim)
// ---------------------------------------------------------------------------
__global__ void __launch_bounds__(256)
rowsum_convert_kernel(const float* __restrict__ A) {
    __shared__ float red[8];
    for (int row = blockIdx.x; row < NN; row += gridDim.x) {
        const float4* a = reinterpret_cast<const float4*>(A + (size_t)row * NN);
        uint2* ah = reinterpret_cast<uint2*>(g_ah + (size_t)row * NN);
        float s = 0.f;
        #pragma unroll 8
        for (int i = threadIdx.x; i < NN / 4; i += 256) {
            float4 v = a[i];
            s += (v.x + v.y) + (v.z + v.w);
            __half2 h01 = __floats2half2_rn(v.x, v.y);
            __half2 h23 = __floats2half2_rn(v.z, v.w);
            uint2 u;
            u.x = *reinterpret_cast<uint32_t*>(&h01);
            u.y = *reinterpret_cast<uint32_t*>(&h23);
            ah[i] = u;
        }
        #pragma unroll
        for (int o = 16; o; o >>= 1) s += __shfl_xor_sync(0xFFFFFFFFu, s, o);
        if ((threadIdx.x & 31) == 0) red[threadIdx.x >> 5] = s;
        __syncthreads();
        if (threadIdx.x < 32) {
            s = (threadIdx.x < 8) ? red[threadIdx.x] : 0.f;
            #pragma unroll
            for (int o = 4; o; o >>= 1) s += __shfl_xor_sync(0xFFFFFFFFu, s, o);
            if (threadIdx.x == 0) g_deg[row] = s;
        }
        __syncthreads();
    }
}

// ---------------------------------------------------------------------------
// Kernel 2: Y[j][k] = fp16( rsqrt(deg[j]) * sum_f X[j][f] * W[f][k] )
// ---------------------------------------------------------------------------
__global__ void xw_kernel(const float* __restrict__ X, const float* __restrict__ W) {
    __shared__ float sW[DIN * DOUT];   // 32 KB
    __shared__ float sX[16 * DIN];     // 8 KB
    int r0 = blockIdx.x * 16;
    for (int i = threadIdx.x; i < DIN * DOUT; i += 256) sW[i] = W[i];
    for (int i = threadIdx.x; i < 16 * DIN; i += 256) {
        int r = i >> 7, f = i & 127;
        sX[i] = X[(size_t)(r0 + r) * DIN + f] * rsqrtf(g_deg[r0 + r]);
    }
    __syncthreads();

    int r  = threadIdx.x >> 4;
    int c0 = (threadIdx.x & 15) * 4;
    float4 acc = make_float4(0.f, 0.f, 0.f, 0.f);
    #pragma unroll 8
    for (int f = 0; f < DIN; f++) {
        float s = sX[r * DIN + f];
        float4 w = *reinterpret_cast<const float4*>(&sW[f * DOUT + c0]);
        acc.x += s * w.x; acc.y += s * w.y; acc.z += s * w.z; acc.w += s * w.w;
    }
    __half2 h01 = __floats2half2_rn(acc.x, acc.y);
    __half2 h23 = __floats2half2_rn(acc.z, acc.w);
    uint2 u;
    u.x = *reinterpret_cast<uint32_t*>(&h01);
    u.y = *reinterpret_cast<uint32_t*>(&h23);
    *reinterpret_cast<uint2*>(&g_yh[(size_t)(r0 + r) * DOUT + c0]) = u;
}

// ---------------------------------------------------------------------------
// Kernel 3: split-K GEMM (fp16 mma.sync) with register-pipelined fragments
// grid (64, 4), block 256 (8 warps: 4 over M x 2 over N), 4-stage pipeline
// ---------------------------------------------------------------------------
__device__ __forceinline__ void load_chunk(uint32_t sbase, int stage, int c,
                                           const __half* __restrict__ Ablk,
                                           const __half* __restrict__ Bblk, int tid) {
    const uint32_t sA = sbase + (uint32_t)stage * A_STAGE_BYTES;
    const uint32_t sB = sbase + SMEM_B_BASE + (uint32_t)stage * B_STAGE_BYTES;
    const __half* ap = Ablk + (size_t)c * K_TILE;
    const __half* bp = Bblk + (size_t)c * K_TILE * DOUT;
    #pragma unroll
    for (int it = 0; it < 4; it++) {
        int idx = tid + 256 * it;
        int row = idx >> 3;
        int cc  = idx & 7;
        uint32_t dst = sA + (uint32_t)row * 128 + ((uint32_t)(cc ^ (row & 7)) << 4);
        CP_ASYNC16(dst, ap + (size_t)row * NN + cc * 8);
    }
    #pragma unroll
    for (int it = 0; it < 2; it++) {
        int idx = tid + 256 * it;
        int kr  = idx >> 3;
        int cc  = idx & 7;
        uint32_t dst = sB + (uint32_t)kr * 128 + ((uint32_t)(cc ^ (kr & 7)) << 4);
        CP_ASYNC16(dst, bp + (size_t)kr * DOUT + cc * 8);
    }
}

__global__ void __launch_bounds__(256, 2)
gemm_kernel() {
    extern __shared__ __align__(128) char smem[];
    const uint32_t sbase = smem_u32(smem);

    const int tid  = threadIdx.x;
    const int lane = tid & 31;
    const int wid  = tid >> 5;
    const int wm   = wid & 3;            // warp M group (32 rows)
    const int wn   = wid >> 2;           // warp N group (32 cols)
    const int Ar0  = wm * 32;
    const int Cn0  = wn * 32;

    const __half* Ablk = g_ah + (size_t)blockIdx.x * M_TILE * NN + (size_t)blockIdx.y * KPER;
    const __half* Bblk = g_yh + (size_t)blockIdx.y * KPER * DOUT;

    // ldmatrix per-lane geometry
    const int a_lrow = lane & 15;
    const int a_lk   = lane >> 4;
    const int b_lk   = lane & 15;
    const int b_ln8  = lane >> 4;

    float acc[2][4][4];
    #pragma unroll
    for (int mi = 0; mi < 2; mi++)
        #pragma unroll
        for (int ni = 0; ni < 4; ni++)
            #pragma unroll
            for (int q = 0; q < 4; q++) acc[mi][ni][q] = 0.f;

    // prologue: stages 0..2
    #pragma unroll
    for (int s = 0; s < STAGES - 1; s++) {
        load_chunk(sbase, s, s, Ablk, Bblk, tid);
        CP_COMMIT();
    }

    for (int c = 0; c < NCHUNK; c++) {
        CP_WAIT2();                       // exactly 3 pending -> chunk c resident
        __syncthreads();

        const int s = c & (STAGES - 1);
        const uint32_t sA = sbase + (uint32_t)s * A_STAGE_BYTES;
        const uint32_t sB = sbase + SMEM_B_BASE + (uint32_t)s * B_STAGE_BYTES;

        // commit a group EVERY iteration (empty at tail) to keep the wait invariant
        if (c + STAGES - 1 < NCHUNK)
            load_chunk(sbase, (c + STAGES - 1) & (STAGES - 1), c + STAGES - 1, Ablk, Bblk, tid);
        CP_COMMIT();

        // register-pipelined fragments: load kk+1's ldsm while mma'ing kk
        uint32_t af[2][2][4];   // [parity][mi][4]
        uint32_t bf[2][2][4];   // [parity][nb][4]

        // load kk = 0 into parity 0
        #pragma unroll
        for (int mi = 0; mi < 2; mi++) {
            int r = Ar0 + mi * 16 + a_lrow;
            ldsm_x4(af[0][mi], sA + (uint32_t)r * 128 +
                               ((uint32_t)((a_lk) ^ (r & 7)) << 4));
        }
        #pragma unroll
        for (int nb = 0; nb < 2; nb++) {
            int kr = b_lk;
            int n  = Cn0 + nb * 16 + b_ln8 * 8;
            ldsm_x4_t(bf[0][nb], sB + (uint32_t)kr * 128 +
                                 ((uint32_t)((n >> 3) ^ (kr & 7)) << 4));
        }

        #pragma unroll
        for (int kk = 0; kk < K_TILE / 16; kk++) {
            const int p  = kk & 1;
            const int pn = p ^ 1;
            if (kk + 1 < K_TILE / 16) {
                #pragma unroll
                for (int mi = 0; mi < 2; mi++) {
                    int r = Ar0 + mi * 16 + a_lrow;
                    ldsm_x4(af[pn][mi], sA + (uint32_t)r * 128 +
                                        ((uint32_t)(((kk + 1) * 2 + a_lk) ^ (r & 7)) << 4));
                }
                #pragma unroll
                for (int nb = 0; nb < 2; nb++) {
                    int kr = (kk + 1) * 16 + b_lk;
                    int n  = Cn0 + nb * 16 + b_ln8 * 8;
                    ldsm_x4_t(bf[pn][nb], sB + (uint32_t)kr * 128 +
                                          ((uint32_t)((n >> 3) ^ (kr & 7)) << 4));
                }
            }
            #pragma unroll
            for (int mi = 0; mi < 2; mi++)
                #pragma unroll
                for (int ni = 0; ni < 4; ni++)
                    mma_f16(acc[mi][ni], af[p][mi],
                            bf[p][ni >> 1][2 * (ni & 1)], bf[p][ni >> 1][2 * (ni & 1) + 1]);
        }
    }

    // epilogue: acc -> g_hpart[split] as fp16 (half2 stores)
    __half* Hp = g_hpart[blockIdx.y];
    const int g = lane >> 2, q = lane & 3;
    const int R0 = blockIdx.x * M_TILE + wm * 32;
    #pragma unroll
    for (int mi = 0; mi < 2; mi++) {
        #pragma unroll
        for (int ni = 0; ni < 4; ni++) {
            int row = R0 + mi * 16 + g;
            int col = Cn0 + ni * 8 + q * 2;
            __half2 h0 = __floats2half2_rn(acc[mi][ni][0], acc[mi][ni][1]);
            __half2 h1 = __floats2half2_rn(acc[mi][ni][2], acc[mi][ni][3]);
            *reinterpret_cast<__half2*>(&Hp[(size_t)row * DOUT + col]) = h0;
            *reinterpret_cast<__half2*>(&Hp[(size_t)(row + 8) * DOUT + col]) = h1;
        }
    }
}

// ---------------------------------------------------------------------------
// Kernel 4: out = relu( d^-1/2_i * sum_s hpart[s] ), fp16 partial reads
// 65536 threads; each handles 8 consecutive cols (one uint4 per partial)
// ---------------------------------------------------------------------------
__global__ void out_kernel(float* __restrict__ out) {
    int t = blockIdx.x * 256 + threadIdx.x;          // 65536 = NN*DOUT/8
    int row = t >> 3;
    int c8  = (t & 7) * 8;
    size_t o = (size_t)row * DOUT + c8;

    uint4 p0 = *reinterpret_cast<const uint4*>(&g_hpart[0][o]);
    uint4 p1 = *reinterpret_cast<const uint4*>(&g_hpart[1][o]);
    uint4 p2 = *reinterpret_cast<const uint4*>(&g_hpart[2][o]);
    uint4 p3 = *reinterpret_cast<const uint4*>(&g_hpart[3][o]);
    float s = rsqrtf(g_deg[row]);

    float r[8];
    const uint32_t* u0 = &p0.x;
    const uint32_t* u1 = &p1.x;
    const uint32_t* u2 = &p2.x;
    const uint32_t* u3 = &p3.x;
    #pragma unroll
    for (int i = 0; i < 4; i++) {
        float2 a = __half22float2(*reinterpret_cast<const __half2*>(&u0[i]));
        float2 b = __half22float2(*reinterpret_cast<const __half2*>(&u1[i]));
        float2 cc = __half22float2(*reinterpret_cast<const __half2*>(&u2[i]));
        float2 d = __half22float2(*reinterpret_cast<const __half2*>(&u3[i]));
        r[2 * i]     = fmaxf((a.x + b.x + cc.x + d.x) * s, 0.f);
        r[2 * i + 1] = fmaxf((a.y + b.y + cc.y + d.y) * s, 0.f);
    }
    float4* op = reinterpret_cast<float4*>(&out[o]);
    op[0] = make_float4(r[0], r[1], r[2], r[3]);
    op[1] = make_float4(r[4], r[5], r[6], r[7]);
}

// ---------------------------------------------------------------------------
// Launch
// ---------------------------------------------------------------------------
extern "C" void kernel_launch(void* const* d_in, const int* in_sizes, int n_in,
                              void* d_out, int out_size) {
    const float* X = (const float*)d_in[0];   // features      [8192, 128]
    const float* A = (const float*)d_in[1];   // adjacency     [8192, 8192]
    const float* W = (const float*)d_in[2];   // weight        [128, 64]
    float* out = (float*)d_out;               // [8192, 64] fp32
    (void)in_sizes; (void)n_in; (void)out_size;

    static bool attr_set = false;
    if (!attr_set) {
        cudaFuncSetAttribute(gemm_kernel, cudaFuncAttributeMaxDynamicSharedMemorySize, SMEM_TOTAL);
        attr_set = true;
    }

    rowsum_convert_kernel<<<1184, 256>>>(A);   // 8 x 148 persistent blocks
    xw_kernel<<<NN / 16, 256>>>(X, W);
    gemm_kernel<<<dim3(NN / M_TILE, SPLITK), 256, SMEM_TOTAL>>>();
    out_kernel<<<256, 256>>>(out);
}